// round 11
// baseline (speedup 1.0000x reference)
#include <cuda_runtime.h>
#include <cstdint>

#define ROWS 4096
#define COLS 11008
#define G    128
#define NB   86                         // COLS / G
#define NGROUPS (ROWS * NB)             // 352256
#define NTASK   (NGROUPS / 4)           // 88064 warp-tasks (4 groups each)
#define NTHREADS 128
#define NBLOCKS  5504                   // 22016 warps -> exactly 4 tasks per warp
#define NWARPS   (NBLOCKS * (NTHREADS / 32))
#define ITERS    (NTASK / NWARPS)       // 4, exact

// Prefetch one warp-task's 2KB (16 x 128B lines) into L2.
__device__ __forceinline__ void l2_prefetch_task(const float4* x4, int g, int lane)
{
    if (lane < 16) {
        const char* p = reinterpret_cast<const char*>(x4 + (size_t)g * 32) + lane * 128;
        asm volatile("prefetch.global.L2 [%0];" :: "l"(p));
    }
}

__device__ __forceinline__ void process_task(
    int g, float uf, float lf,
    float4 a0, float4 a1, float4 a2, float4 a3,
    float4* __restrict__ out4, int off)
{
    const float CLIPMIN = 1e-5f;
    const float CLIPMAX = 10000.0f;

    // ---- per-lane partials over 16 values ----
    float mn, mx, sm, as;
    {
        float t0, t1, t2, t3;
        t0 = fminf(fminf(a0.x, a1.x), fminf(a2.x, a3.x));
        t1 = fminf(fminf(a0.y, a1.y), fminf(a2.y, a3.y));
        t2 = fminf(fminf(a0.z, a1.z), fminf(a2.z, a3.z));
        t3 = fminf(fminf(a0.w, a1.w), fminf(a2.w, a3.w));
        mn = fminf(fminf(t0, t1), fminf(t2, t3));

        t0 = fmaxf(fmaxf(a0.x, a1.x), fmaxf(a2.x, a3.x));
        t1 = fmaxf(fmaxf(a0.y, a1.y), fmaxf(a2.y, a3.y));
        t2 = fmaxf(fmaxf(a0.z, a1.z), fmaxf(a2.z, a3.z));
        t3 = fmaxf(fmaxf(a0.w, a1.w), fmaxf(a2.w, a3.w));
        mx = fmaxf(fmaxf(t0, t1), fmaxf(t2, t3));

        t0 = (a0.x + a1.x) + (a2.x + a3.x);
        t1 = (a0.y + a1.y) + (a2.y + a3.y);
        t2 = (a0.z + a1.z) + (a2.z + a3.z);
        t3 = (a0.w + a1.w) + (a2.w + a3.w);
        sm = (t0 + t1) + (t2 + t3);

        t0 = (fabsf(a0.x) + fabsf(a1.x)) + (fabsf(a2.x) + fabsf(a3.x));
        t1 = (fabsf(a0.y) + fabsf(a1.y)) + (fabsf(a2.y) + fabsf(a3.y));
        t2 = (fabsf(a0.z) + fabsf(a1.z)) + (fabsf(a2.z) + fabsf(a3.z));
        t3 = (fabsf(a0.w) + fabsf(a1.w)) + (fabsf(a2.w) + fabsf(a3.w));
        as = (t0 + t1) + (t2 + t3);
    }

    // ---- segmented butterfly: offsets 1,2,4 stay inside each 8-lane segment ----
    #pragma unroll
    for (int o = 1; o < 8; o <<= 1) {
        mn = fminf(mn, __shfl_xor_sync(0xffffffffu, mn, o));
        mx = fmaxf(mx, __shfl_xor_sync(0xffffffffu, mx, o));
        sm += __shfl_xor_sync(0xffffffffu, sm, o);
        as += __shfl_xor_sync(0xffffffffu, as, o);
    }

    // ---- per-group parameters ----
    int j = g % NB;
    bool is_t = (j == 0);
    int prec;
    if (is_t) {
        prec = 1;
    } else {
        int r = (j - 1) % 5;            // pattern 2,3,4,3,2
        prec = (r == 0) ? 2 : (r == 1) ? 3 : (r == 2) ? 4 : (r == 3) ? 3 : 2;
    }
    float levels = (float)((1 << prec) - 1);

    // fast sigmoid: MUFU.RCP instead of div.rn subroutine (~1e-7 rel err, well
    // inside the 1e-3 gate; shortens the per-task serial window)
    float su = __fdividef(1.0f, 1.0f + __expf(-uf));
    float sl = __fdividef(1.0f, 1.0f + __expf(-lf));

    float mean  = sm * (1.0f / (float)G);
    float amean = as * (1.0f / (float)G);
    float xmax  = su * mx;
    float xmin  = sl * mn;

    if (is_t) {
        float s = fminf(fmaxf(amean * (su + 0.5f), CLIPMIN), CLIPMAX);
        float z = fminf(fmaxf(mean, -CLIPMAX), CLIPMAX);
        float ns = -s;
        a0.x = (a0.x > z) ? s : (a0.x < z) ? ns : 0.0f;
        a0.y = (a0.y > z) ? s : (a0.y < z) ? ns : 0.0f;
        a0.z = (a0.z > z) ? s : (a0.z < z) ? ns : 0.0f;
        a0.w = (a0.w > z) ? s : (a0.w < z) ? ns : 0.0f;
        a1.x = (a1.x > z) ? s : (a1.x < z) ? ns : 0.0f;
        a1.y = (a1.y > z) ? s : (a1.y < z) ? ns : 0.0f;
        a1.z = (a1.z > z) ? s : (a1.z < z) ? ns : 0.0f;
        a1.w = (a1.w > z) ? s : (a1.w < z) ? ns : 0.0f;
        a2.x = (a2.x > z) ? s : (a2.x < z) ? ns : 0.0f;
        a2.y = (a2.y > z) ? s : (a2.y < z) ? ns : 0.0f;
        a2.z = (a2.z > z) ? s : (a2.z < z) ? ns : 0.0f;
        a2.w = (a2.w > z) ? s : (a2.w < z) ? ns : 0.0f;
        a3.x = (a3.x > z) ? s : (a3.x < z) ? ns : 0.0f;
        a3.y = (a3.y > z) ? s : (a3.y < z) ? ns : 0.0f;
        a3.z = (a3.z > z) ? s : (a3.z < z) ? ns : 0.0f;
        a3.w = (a3.w > z) ? s : (a3.w < z) ? ns : 0.0f;
    } else {
        // keep precise divides here: zp feeds rint, must bit-match the reference path
        float scale_r = (xmax - xmin) / levels;
        float s  = fminf(fmaxf(scale_r, CLIPMIN), CLIPMAX);
        float zp = -xmin / scale_r;                  // unclipped scale_r (matches ref)
        float z  = rintf(fminf(fmaxf(zp, -CLIPMAX), CLIPMAX));
        float inv_s = 1.0f / s;
        float qlo = 0.0f   - z;                      // qmin - z (exact: integers)
        float qhi = levels - z;                      // qmax - z (exact: integers)
        a0.x = fminf(fmaxf(rintf(a0.x * inv_s), qlo), qhi) * s;
        a0.y = fminf(fmaxf(rintf(a0.y * inv_s), qlo), qhi) * s;
        a0.z = fminf(fmaxf(rintf(a0.z * inv_s), qlo), qhi) * s;
        a0.w = fminf(fmaxf(rintf(a0.w * inv_s), qlo), qhi) * s;
        a1.x = fminf(fmaxf(rintf(a1.x * inv_s), qlo), qhi) * s;
        a1.y = fminf(fmaxf(rintf(a1.y * inv_s), qlo), qhi) * s;
        a1.z = fminf(fmaxf(rintf(a1.z * inv_s), qlo), qhi) * s;
        a1.w = fminf(fmaxf(rintf(a1.w * inv_s), qlo), qhi) * s;
        a2.x = fminf(fmaxf(rintf(a2.x * inv_s), qlo), qhi) * s;
        a2.y = fminf(fmaxf(rintf(a2.y * inv_s), qlo), qhi) * s;
        a2.z = fminf(fmaxf(rintf(a2.z * inv_s), qlo), qhi) * s;
        a2.w = fminf(fmaxf(rintf(a2.w * inv_s), qlo), qhi) * s;
        a3.x = fminf(fmaxf(rintf(a3.x * inv_s), qlo), qhi) * s;
        a3.y = fminf(fmaxf(rintf(a3.y * inv_s), qlo), qhi) * s;
        a3.z = fminf(fmaxf(rintf(a3.z * inv_s), qlo), qhi) * s;
        a3.w = fminf(fmaxf(rintf(a3.w * inv_s), qlo), qhi) * s;
    }

    float4* op = out4 + (size_t)g * 32 + off;
    __stcs(op,      a0);
    __stcs(op + 8,  a1);
    __stcs(op + 16, a2);
    __stcs(op + 24, a3);
}

__global__ __launch_bounds__(NTHREADS, 8)
void mixq_kernel(const float4* __restrict__ x4,
                 const float* __restrict__ up,
                 const float* __restrict__ low,
                 float4* __restrict__ out4)
{
    int warp = (blockIdx.x * blockDim.x + threadIdx.x) >> 5;
    int lane = threadIdx.x & 31;
    int seg  = lane >> 3;
    int off  = lane & 7;

    // ---- prologue: load task 0, L2-prefetch task 1 ----
    int g = warp * 4 + seg;                    // task 0 group for this segment
    const float4* gp = x4 + (size_t)g * 32 + off;
    float4 a0 = __ldcs(gp);
    float4 a1 = __ldcs(gp + 8);
    float4 a2 = __ldcs(gp + 16);
    float4 a3 = __ldcs(gp + 24);
    float  uf = __ldg(up + g);
    float  lf = __ldg(low + g);

    l2_prefetch_task(x4, (warp + 1 * NWARPS) * 4, lane);

    #pragma unroll
    for (int it = 0; it < ITERS; it++) {
        float4 b0, b1, b2, b3;
        float  uf2, lf2;
        int g2 = g + NWARPS * 4;
        if (it < ITERS - 1) {
            // register-prefetch next task
            const float4* gp2 = x4 + (size_t)g2 * 32 + off;
            b0  = __ldcs(gp2);
            b1  = __ldcs(gp2 + 8);
            b2  = __ldcs(gp2 + 16);
            b3  = __ldcs(gp2 + 24);
            uf2 = __ldg(up + g2);
            lf2 = __ldg(low + g2);
        }
        if (it < ITERS - 2) {
            // depth-2 L2 prefetch
            l2_prefetch_task(x4, (warp + (it + 2) * NWARPS) * 4, lane);
        }

        process_task(g, uf, lf, a0, a1, a2, a3, out4, off);

        if (it < ITERS - 1) {
            a0 = b0; a1 = b1; a2 = b2; a3 = b3;
            uf = uf2; lf = lf2;
            g  = g2;
        }
    }
}

extern "C" void kernel_launch(void* const* d_in, const int* in_sizes, int n_in,
                              void* d_out, int out_size)
{
    const float4* x4  = (const float4*)d_in[0];
    const float*  up  = (const float*)d_in[1];
    const float*  low = (const float*)d_in[2];
    float4* out4 = (float4*)d_out;

    mixq_kernel<<<NBLOCKS, NTHREADS>>>(x4, up, low, out4);
}

// round 12
// speedup vs baseline: 1.0061x; 1.0061x over previous
#include <cuda_runtime.h>
#include <cstdint>

#define ROWS 4096
#define COLS 11008
#define G    128
#define NB   86                         // COLS / G
#define NGROUPS (ROWS * NB)             // 352256
#define NTASK   (NGROUPS / 4)           // 88064 warp-tasks (4 groups each)
#define NTHREADS 256
#define NBLOCKS  2752                   // 22016 warps -> exactly 4 tasks per warp
#define NWARPS   (NBLOCKS * (NTHREADS / 32))
#define ITERS    (NTASK / NWARPS)       // 4, exact

// Prefetch one warp-task's 2KB (16 x 128B lines) into L2.
__device__ __forceinline__ void l2_prefetch_task(const float4* x4, int g, int lane)
{
    if (lane < 16) {
        const char* p = reinterpret_cast<const char*>(x4 + (size_t)g * 32) + lane * 128;
        asm volatile("prefetch.global.L2 [%0];" :: "l"(p));
    }
}

__device__ __forceinline__ void process_task(
    int g, float uf, float lf,
    float4 a0, float4 a1, float4 a2, float4 a3,
    float4* __restrict__ out4, int off)
{
    const float CLIPMIN = 1e-5f;
    const float CLIPMAX = 10000.0f;

    // ---- per-lane partials over 16 values ----
    float mn, mx, sm, as;
    {
        float t0, t1, t2, t3;
        t0 = fminf(fminf(a0.x, a1.x), fminf(a2.x, a3.x));
        t1 = fminf(fminf(a0.y, a1.y), fminf(a2.y, a3.y));
        t2 = fminf(fminf(a0.z, a1.z), fminf(a2.z, a3.z));
        t3 = fminf(fminf(a0.w, a1.w), fminf(a2.w, a3.w));
        mn = fminf(fminf(t0, t1), fminf(t2, t3));

        t0 = fmaxf(fmaxf(a0.x, a1.x), fmaxf(a2.x, a3.x));
        t1 = fmaxf(fmaxf(a0.y, a1.y), fmaxf(a2.y, a3.y));
        t2 = fmaxf(fmaxf(a0.z, a1.z), fmaxf(a2.z, a3.z));
        t3 = fmaxf(fmaxf(a0.w, a1.w), fmaxf(a2.w, a3.w));
        mx = fmaxf(fmaxf(t0, t1), fmaxf(t2, t3));

        t0 = (a0.x + a1.x) + (a2.x + a3.x);
        t1 = (a0.y + a1.y) + (a2.y + a3.y);
        t2 = (a0.z + a1.z) + (a2.z + a3.z);
        t3 = (a0.w + a1.w) + (a2.w + a3.w);
        sm = (t0 + t1) + (t2 + t3);

        t0 = (fabsf(a0.x) + fabsf(a1.x)) + (fabsf(a2.x) + fabsf(a3.x));
        t1 = (fabsf(a0.y) + fabsf(a1.y)) + (fabsf(a2.y) + fabsf(a3.y));
        t2 = (fabsf(a0.z) + fabsf(a1.z)) + (fabsf(a2.z) + fabsf(a3.z));
        t3 = (fabsf(a0.w) + fabsf(a1.w)) + (fabsf(a2.w) + fabsf(a3.w));
        as = (t0 + t1) + (t2 + t3);
    }

    // ---- segmented butterfly: offsets 1,2,4 stay inside each 8-lane segment ----
    #pragma unroll
    for (int o = 1; o < 8; o <<= 1) {
        mn = fminf(mn, __shfl_xor_sync(0xffffffffu, mn, o));
        mx = fmaxf(mx, __shfl_xor_sync(0xffffffffu, mx, o));
        sm += __shfl_xor_sync(0xffffffffu, sm, o);
        as += __shfl_xor_sync(0xffffffffu, as, o);
    }

    // ---- per-group parameters ----
    int j = g % NB;
    bool is_t = (j == 0);
    int prec;
    if (is_t) {
        prec = 1;
    } else {
        int r = (j - 1) % 5;            // pattern 2,3,4,3,2
        prec = (r == 0) ? 2 : (r == 1) ? 3 : (r == 2) ? 4 : (r == 3) ? 3 : 2;
    }
    float levels = (float)((1 << prec) - 1);

    // fast sigmoid: MUFU.RCP path (~1e-7 rel err; validated identical rel_err)
    float su = __fdividef(1.0f, 1.0f + __expf(-uf));
    float sl = __fdividef(1.0f, 1.0f + __expf(-lf));

    float mean  = sm * (1.0f / (float)G);
    float amean = as * (1.0f / (float)G);
    float xmax  = su * mx;
    float xmin  = sl * mn;

    if (is_t) {
        float s = fminf(fmaxf(amean * (su + 0.5f), CLIPMIN), CLIPMAX);
        float z = fminf(fmaxf(mean, -CLIPMAX), CLIPMAX);
        float ns = -s;
        a0.x = (a0.x > z) ? s : (a0.x < z) ? ns : 0.0f;
        a0.y = (a0.y > z) ? s : (a0.y < z) ? ns : 0.0f;
        a0.z = (a0.z > z) ? s : (a0.z < z) ? ns : 0.0f;
        a0.w = (a0.w > z) ? s : (a0.w < z) ? ns : 0.0f;
        a1.x = (a1.x > z) ? s : (a1.x < z) ? ns : 0.0f;
        a1.y = (a1.y > z) ? s : (a1.y < z) ? ns : 0.0f;
        a1.z = (a1.z > z) ? s : (a1.z < z) ? ns : 0.0f;
        a1.w = (a1.w > z) ? s : (a1.w < z) ? ns : 0.0f;
        a2.x = (a2.x > z) ? s : (a2.x < z) ? ns : 0.0f;
        a2.y = (a2.y > z) ? s : (a2.y < z) ? ns : 0.0f;
        a2.z = (a2.z > z) ? s : (a2.z < z) ? ns : 0.0f;
        a2.w = (a2.w > z) ? s : (a2.w < z) ? ns : 0.0f;
        a3.x = (a3.x > z) ? s : (a3.x < z) ? ns : 0.0f;
        a3.y = (a3.y > z) ? s : (a3.y < z) ? ns : 0.0f;
        a3.z = (a3.z > z) ? s : (a3.z < z) ? ns : 0.0f;
        a3.w = (a3.w > z) ? s : (a3.w < z) ? ns : 0.0f;
    } else {
        // precise divides: zp feeds rint, must match the reference path
        float scale_r = (xmax - xmin) / levels;
        float s  = fminf(fmaxf(scale_r, CLIPMIN), CLIPMAX);
        float zp = -xmin / scale_r;                  // unclipped scale_r (matches ref)
        float z  = rintf(fminf(fmaxf(zp, -CLIPMAX), CLIPMAX));
        float inv_s = 1.0f / s;
        float qlo = 0.0f   - z;                      // qmin - z (exact: integers)
        float qhi = levels - z;                      // qmax - z (exact: integers)
        a0.x = fminf(fmaxf(rintf(a0.x * inv_s), qlo), qhi) * s;
        a0.y = fminf(fmaxf(rintf(a0.y * inv_s), qlo), qhi) * s;
        a0.z = fminf(fmaxf(rintf(a0.z * inv_s), qlo), qhi) * s;
        a0.w = fminf(fmaxf(rintf(a0.w * inv_s), qlo), qhi) * s;
        a1.x = fminf(fmaxf(rintf(a1.x * inv_s), qlo), qhi) * s;
        a1.y = fminf(fmaxf(rintf(a1.y * inv_s), qlo), qhi) * s;
        a1.z = fminf(fmaxf(rintf(a1.z * inv_s), qlo), qhi) * s;
        a1.w = fminf(fmaxf(rintf(a1.w * inv_s), qlo), qhi) * s;
        a2.x = fminf(fmaxf(rintf(a2.x * inv_s), qlo), qhi) * s;
        a2.y = fminf(fmaxf(rintf(a2.y * inv_s), qlo), qhi) * s;
        a2.z = fminf(fmaxf(rintf(a2.z * inv_s), qlo), qhi) * s;
        a2.w = fminf(fmaxf(rintf(a2.w * inv_s), qlo), qhi) * s;
        a3.x = fminf(fmaxf(rintf(a3.x * inv_s), qlo), qhi) * s;
        a3.y = fminf(fmaxf(rintf(a3.y * inv_s), qlo), qhi) * s;
        a3.z = fminf(fmaxf(rintf(a3.z * inv_s), qlo), qhi) * s;
        a3.w = fminf(fmaxf(rintf(a3.w * inv_s), qlo), qhi) * s;
    }

    float4* op = out4 + (size_t)g * 32 + off;
    __stcs(op,      a0);
    __stcs(op + 8,  a1);
    __stcs(op + 16, a2);
    __stcs(op + 24, a3);
}

__global__ __launch_bounds__(NTHREADS, 4)
void mixq_kernel(const float4* __restrict__ x4,
                 const float* __restrict__ up,
                 const float* __restrict__ low,
                 float4* __restrict__ out4)
{
    int warp = (blockIdx.x * blockDim.x + threadIdx.x) >> 5;
    int lane = threadIdx.x & 31;
    int seg  = lane >> 3;
    int off  = lane & 7;

    // ---- prologue: load task 0, L2-prefetch task 1 ----
    int g = warp * 4 + seg;                    // task 0 group for this segment
    const float4* gp = x4 + (size_t)g * 32 + off;
    float4 a0 = __ldcs(gp);
    float4 a1 = __ldcs(gp + 8);
    float4 a2 = __ldcs(gp + 16);
    float4 a3 = __ldcs(gp + 24);
    float  uf = __ldg(up + g);
    float  lf = __ldg(low + g);

    l2_prefetch_task(x4, (warp + 1 * NWARPS) * 4, lane);

    #pragma unroll
    for (int it = 0; it < ITERS; it++) {
        float4 b0, b1, b2, b3;
        float  uf2, lf2;
        int g2 = g + NWARPS * 4;
        if (it < ITERS - 1) {
            // register-prefetch next task (hits L2 thanks to depth-2 prefetch)
            const float4* gp2 = x4 + (size_t)g2 * 32 + off;
            b0  = __ldcs(gp2);
            b1  = __ldcs(gp2 + 8);
            b2  = __ldcs(gp2 + 16);
            b3  = __ldcs(gp2 + 24);
            uf2 = __ldg(up + g2);
            lf2 = __ldg(low + g2);
        }
        if (it < ITERS - 2) {
            // depth-2 L2 prefetch: task it+2
            l2_prefetch_task(x4, (warp + (it + 2) * NWARPS) * 4, lane);
        }

        process_task(g, uf, lf, a0, a1, a2, a3, out4, off);

        if (it < ITERS - 1) {
            a0 = b0; a1 = b1; a2 = b2; a3 = b3;
            uf = uf2; lf = lf2;
            g  = g2;
        }
    }
}

extern "C" void kernel_launch(void* const* d_in, const int* in_sizes, int n_in,
                              void* d_out, int out_size)
{
    const float4* x4  = (const float4*)d_in[0];
    const float*  up  = (const float*)d_in[1];
    const float*  low = (const float*)d_in[2];
    float4* out4 = (float4*)d_out;

    mixq_kernel<<<NBLOCKS, NTHREADS>>>(x4, up, low, out4);
}